// round 11
// baseline (speedup 1.0000x reference)
#include <cuda_runtime.h>

// ---------------- problem constants ----------------
#define HW        512
#define PLANES    48          // 16 batch * 3 channels
#define NPIX      12582912.0  // 48*512*512
#define TW        64
#define TH        32
#define SW        80          // halo cols stored: [x0-8, x0+72), 16B-aligned quads
#define SH        42          // TH + 10
#define SSTR      84          // smem row stride (floats); 336B%128=80 -> conflict-free f4 rows
#define XOFF      3           // conv column c lives at smem col c+XOFF ([x0-5] -> col 3)
#define NTHREADS  320
#define NBLOCKS   6144u       // 8*16*48

#define C1F 0.0001f
#define C2F 0.0009f

// Gaussian(sigma=1.5) centered at 5.5, normalized (sum = 0.99999982).
// Tap precision is load-bearing (-3.2e-4 tap-scale error amplifies ~500x
// through the C2=9e-4 term). constexpr + literal indices -> FFMA-imm (rt=1).
__device__ constexpr float GW[11] = {
    0.00032030f, 0.00295566f, 0.01748770f, 0.06634250f, 0.16137290f,
    0.25168100f, 0.25168100f, 0.16137290f, 0.06634250f, 0.01748770f,
    0.00295566f
};

__device__ float g_part[NBLOCKS];
__device__ unsigned int g_count = 0;   // self-resetting ticket (inc wraps)

// FMA-only reciprocal: magic seed + 2 Newton steps (err ~1.4e-6, << budget).
// Avoids MUFU.RCP (rt_SMSP=8 -> chip-wide floor at 12.6M divides).
__device__ __forceinline__ float fast_rcp(float d) {
    float r = __int_as_float(0x7EF311C3 - __float_as_int(d));
#pragma unroll
    for (int it = 0; it < 2; ++it) {
        float t = fmaf(-d, r, 1.0f);
        r = fmaf(r, t, r);
    }
    return r;
}

// SSIM via sum/difference transform (4 convolutions):
//   s=a+b, d=a-b;  S=conv(s), D=conv(d), P=conv(s^2), Q=conv(d^2)
//   4*mu1mu2 = S^2-D^2;  2*(mu1^2+mu2^2) = S^2+D^2
//   4*sigma12 = (P-Q)-(S^2-D^2);  2*(sig1^2+sig2^2) = (P+Q)-(S^2+D^2)

#define SS(r, c)      s_s[(r) * SSTR + (c) + XOFF]
#define SD(r, c)      s_d[(r) * SSTR + (c) + XOFF]
#define SMID(q, r, c) s_mid[((q) * TH + (r)) * SSTR + (c)]

__global__ void __launch_bounds__(NTHREADS, 2)
ssim_main_kernel(const float* __restrict__ img1, const float* __restrict__ img2,
                 float* __restrict__ out) {
    extern __shared__ float smem[];
    float* s_s   = smem;                         // SH * SSTR  (a+b)
    float* s_d   = smem + SH * SSTR;             // SH * SSTR  (a-b)
    float* s_mid = smem + 2 * SH * SSTR;         // 4 * TH * SSTR

    const int tid   = threadIdx.x;
    const int plane = blockIdx.z;
    const int x0    = blockIdx.x * TW;
    const int y0    = blockIdx.y * TH;

    const float* __restrict__ p1 = img1 + (size_t)plane * HW * HW;
    const float* __restrict__ p2 = img2 + (size_t)plane * HW * HW;

    // ---------- Phase 1: vectorized halo load ----------
    // thread <-> (row stripe, 16B quad): 20 quads x 42 rows per image.
    // Interior quads: LDG.128 + STS.128 (no per-element math); edge quads
    // (only in border blocks / out-of-image rows) fall back to predicated
    // scalar loads. One %/ / pair per thread total.
    {
        const int q   = tid % 20;        // quad index within row
        const int r0  = tid / 20;        // 0..15
        const int gx4 = x0 - 8 + q * 4;  // 16B-aligned global col of quad
        const bool xfull = (gx4 >= 0) && (gx4 + 3 < HW);
#pragma unroll
        for (int sweep = 0; sweep < 3; ++sweep) {
            const int r = r0 + sweep * 16;
            if (r < SH) {
                const int gy = y0 - 5 + r;
                const bool yin = (unsigned)gy < (unsigned)HW;
                float4 va = make_float4(0.f, 0.f, 0.f, 0.f);
                float4 vb = make_float4(0.f, 0.f, 0.f, 0.f);
                if (yin) {
                    if (xfull) {
                        va = *reinterpret_cast<const float4*>(p1 + gy * HW + gx4);
                        vb = *reinterpret_cast<const float4*>(p2 + gy * HW + gx4);
                    } else {
                        float* pa = reinterpret_cast<float*>(&va);
                        float* pb = reinterpret_cast<float*>(&vb);
#pragma unroll
                        for (int e = 0; e < 4; ++e) {
                            const int gx = gx4 + e;
                            if ((unsigned)gx < (unsigned)HW) {
                                pa[e] = p1[gy * HW + gx];
                                pb[e] = p2[gy * HW + gx];
                            }
                        }
                    }
                }
                float4 vs, vd;
                vs.x = va.x + vb.x; vs.y = va.y + vb.y;
                vs.z = va.z + vb.z; vs.w = va.w + vb.w;
                vd.x = va.x - vb.x; vd.y = va.y - vb.y;
                vd.z = va.z - vb.z; vd.w = va.w - vb.w;
                *reinterpret_cast<float4*>(&s_s[r * SSTR + q * 4]) = vs;
                *reinterpret_cast<float4*>(&s_d[r * SSTR + q * 4]) = vd;
            }
        }
    }
    __syncthreads();

    // ---------- Phase 2: vertical 11-tap conv of s, d, s^2, d^2 ----------
    if (tid < 296) {                 // 74 columns * 4 row-groups of 8
        const int x  = tid % 74;
        const int yb = (tid / 74) * 8;

        float aS[8], aD[8], aP[8], aQ[8];
#pragma unroll
        for (int r = 0; r < 8; ++r) { aS[r] = 0.f; aD[r] = 0.f; aP[r] = 0.f; aQ[r] = 0.f; }
#pragma unroll
        for (int jj = 0; jj < 18; ++jj) {
            const float vs  = SS(yb + jj, x);
            const float vd  = SD(yb + jj, x);
            const float vss = vs * vs;
            const float vdd = vd * vd;
#pragma unroll
            for (int r = 0; r < 8; ++r) {
                const int j = jj - r;
                if (0 <= j && j < 11) {
                    aS[r] = fmaf(GW[j], vs,  aS[r]);
                    aD[r] = fmaf(GW[j], vd,  aD[r]);
                    aP[r] = fmaf(GW[j], vss, aP[r]);
                    aQ[r] = fmaf(GW[j], vdd, aQ[r]);
                }
            }
        }
#pragma unroll
        for (int r = 0; r < 8; ++r) {
            SMID(0, yb + r, x) = aS[r];
            SMID(1, yb + r, x) = aD[r];
            SMID(2, yb + r, x) = aP[r];
            SMID(3, yb + r, x) = aQ[r];
        }
    }
    __syncthreads();

    // ---------- Phase 3: horizontal 11-tap conv + SSIM ----------
    float lsum = 0.f;
    if (tid < 256) {                  // 32 rows * 8 column-groups of 8
        const int y  = tid >> 3;
        const int xb = (tid & 7) * 8;

        float o[4][8];
#pragma unroll
        for (int q = 0; q < 4; ++q) {
            const float4* vp = reinterpret_cast<const float4*>(&SMID(q, y, xb));
            float m[20];
#pragma unroll
            for (int k = 0; k < 5; ++k) {
                const float4 v = vp[k];
                m[4 * k + 0] = v.x;
                m[4 * k + 1] = v.y;
                m[4 * k + 2] = v.z;
                m[4 * k + 3] = v.w;
            }
#pragma unroll
            for (int r = 0; r < 8; ++r) {
                float s = GW[0] * m[r];
#pragma unroll
                for (int i = 1; i < 11; ++i) s = fmaf(GW[i], m[r + i], s);
                o[q][r] = s;
            }
        }
#pragma unroll
        for (int r = 0; r < 8; ++r) {
            const float S = o[0][r], D = o[1][r], P = o[2][r], Q = o[3][r];
            const float S2 = S * S;
            const float D2 = D * D;
            const float t1 = S2 - D2;       // 4*mu1mu2
            const float t2 = S2 + D2;       // 2*(mu1^2+mu2^2)
            const float t5 = (P - Q) - t1;  // 4*sigma12
            const float t6 = (P + Q) - t2;  // 2*(sig1^2+sig2^2)
            const float num = fmaf(0.5f, t1, C1F) * fmaf(0.5f, t5, C2F);
            const float den = fmaf(0.5f, t2, C1F) * fmaf(0.5f, t6, C2F);
            lsum = fmaf(num, fast_rcp(den), lsum);
        }
    }

    // ---------- In-block reduction ----------
#pragma unroll
    for (int off = 16; off > 0; off >>= 1)
        lsum += __shfl_down_sync(0xffffffffu, lsum, off);

    __shared__ float  warp_sums[NTHREADS / 32];
    __shared__ unsigned s_last;
    const int wid  = tid >> 5;
    const int lane = tid & 31;
    if (lane == 0) warp_sums[wid] = lsum;
    __syncthreads();

    // ---------- Fence-free last-block reduction ----------
    if (tid == 0) {
        float s = 0.f;
#pragma unroll
        for (int w = 0; w < NTHREADS / 32; ++w) s += warp_sums[w];
        const int bid = (blockIdx.z * gridDim.y + blockIdx.y) * gridDim.x + blockIdx.x;
        g_part[bid] = s;
        unsigned ticket;
        asm volatile("atom.acq_rel.gpu.global.inc.u32 %0, [%1], %2;"
                     : "=r"(ticket)
                     : "l"(&g_count), "r"(NBLOCKS - 1u)
                     : "memory");
        s_last = (ticket == NBLOCKS - 1u) ? 1u : 0u;
    }
    __syncthreads();

    if (s_last) {
        double d = 0.0;
        for (int i = tid; i < (int)NBLOCKS; i += NTHREADS) d += (double)g_part[i];
#pragma unroll
        for (int off = 16; off > 0; off >>= 1)
            d += __shfl_down_sync(0xffffffffu, d, off);
        __shared__ double wsum[NTHREADS / 32];
        if (lane == 0) wsum[wid] = d;
        __syncthreads();
        if (tid == 0) {
            double t = 0.0;
#pragma unroll
            for (int w = 0; w < NTHREADS / 32; ++w) t += wsum[w];
            out[0] = (float)(t * (1.0 / NPIX));
        }
    }
}

extern "C" void kernel_launch(void* const* d_in, const int* in_sizes, int n_in,
                              void* d_out, int out_size) {
    const float* img1 = (const float*)d_in[0];
    const float* img2 = (const float*)d_in[1];
    float* out = (float*)d_out;

    const int smem_bytes = (2 * SH * SSTR + 4 * TH * SSTR) * (int)sizeof(float); // 71232
    cudaFuncSetAttribute(ssim_main_kernel,
                         cudaFuncAttributeMaxDynamicSharedMemorySize, smem_bytes);

    dim3 grid(HW / TW, HW / TH, PLANES);   // 8 x 16 x 48
    ssim_main_kernel<<<grid, NTHREADS, smem_bytes>>>(img1, img2, out);
}

// round 12
// speedup vs baseline: 1.0042x; 1.0042x over previous
#include <cuda_runtime.h>

// ---------------- problem constants ----------------
#define HW        512
#define PLANES    48          // 16 batch * 3 channels
#define NPIX      12582912.0  // 48*512*512
#define TW        64
#define TH        32
#define SW        80          // halo cols stored: [x0-8, x0+72), 16B-aligned quads
#define SH        42          // TH + 10
#define SSTR      84          // smem row stride (floats); 336B%128=80 -> conflict-free f4 rows
#define XOFF      3           // conv column c lives at smem col c+XOFF ([x0-5] -> col 3)
#define NTHREADS  320
#define NBLOCKS   6144u       // 8*16*48

#define C1F 0.0001f
#define C2F 0.0009f

// Gaussian(sigma=1.5) centered at 5.5, normalized (sum = 0.99999982).
// Tap precision is load-bearing (-3.2e-4 tap-scale error amplifies ~500x
// through the C2=9e-4 term). constexpr + literal indices -> FFMA-imm (rt=1).
__device__ constexpr float GW[11] = {
    0.00032030f, 0.00295566f, 0.01748770f, 0.06634250f, 0.16137290f,
    0.25168100f, 0.25168100f, 0.16137290f, 0.06634250f, 0.01748770f,
    0.00295566f
};

__device__ float g_part[NBLOCKS];
__device__ unsigned int g_count = 0;   // self-resetting ticket (inc wraps)

// FMA-only reciprocal: magic seed + 2 Newton steps (err ~1.4e-6, << budget).
// Avoids MUFU.RCP (rt_SMSP=8 -> chip-wide floor at 12.6M divides).
__device__ __forceinline__ float fast_rcp(float d) {
    float r = __int_as_float(0x7EF311C3 - __float_as_int(d));
#pragma unroll
    for (int it = 0; it < 2; ++it) {
        float t = fmaf(-d, r, 1.0f);
        r = fmaf(r, t, r);
    }
    return r;
}

// SSIM via sum/difference transform (4 convolutions):
//   s=a+b, d=a-b;  S=conv(s), D=conv(d), P=conv(s^2), Q=conv(d^2)
//   4*mu1mu2 = S^2-D^2;  2*(mu1^2+mu2^2) = S^2+D^2
//   4*sigma12 = (P-Q)-(S^2-D^2);  2*(sig1^2+sig2^2) = (P+Q)-(S^2+D^2)

#define SS(r, c)      s_s[(r) * SSTR + (c) + XOFF]
#define SD(r, c)      s_d[(r) * SSTR + (c) + XOFF]
#define SMID(q, r, c) s_mid[((q) * TH + (r)) * SSTR + (c)]

__global__ void __launch_bounds__(NTHREADS, 2)
ssim_main_kernel(const float* __restrict__ img1, const float* __restrict__ img2,
                 float* __restrict__ out) {
    extern __shared__ float smem[];
    float* s_s   = smem;                         // SH * SSTR  (a+b)
    float* s_d   = smem + SH * SSTR;             // SH * SSTR  (a-b)
    float* s_mid = smem + 2 * SH * SSTR;         // 4 * TH * SSTR

    const int tid   = threadIdx.x;
    const int plane = blockIdx.z;
    const int x0    = blockIdx.x * TW;
    const int y0    = blockIdx.y * TH;

    const float* __restrict__ p1 = img1 + (size_t)plane * HW * HW;
    const float* __restrict__ p2 = img2 + (size_t)plane * HW * HW;

    // ---------- Phase 1: vectorized halo load, loads batched for MLP=6 ----
    // R11 post-mortem: interleaving load->store per sweep collapsed MLP to 2
    // and exposed LDG latency. Here ALL six LDG.128s issue before any compute
    // or STS (lat/MLP: 577/6 vs 577/2 per B300 model).
    {
        const int q   = tid % 20;        // quad index within row
        const int r0  = tid / 20;        // 0..15
        const int gx4 = x0 - 8 + q * 4;  // 16B-aligned global col of quad
        const bool xfull = (gx4 >= 0) && (gx4 + 3 < HW);

        float4 va[3], vb[3];
#pragma unroll
        for (int s = 0; s < 3; ++s) {
            const int r  = r0 + s * 16;
            const int gy = y0 - 5 + r;
            const bool yin = (r < SH) && ((unsigned)gy < (unsigned)HW);
            va[s] = make_float4(0.f, 0.f, 0.f, 0.f);
            vb[s] = make_float4(0.f, 0.f, 0.f, 0.f);
            if (yin) {
                if (xfull) {
                    va[s] = *reinterpret_cast<const float4*>(p1 + gy * HW + gx4);
                    vb[s] = *reinterpret_cast<const float4*>(p2 + gy * HW + gx4);
                } else {
                    float* pa = reinterpret_cast<float*>(&va[s]);
                    float* pb = reinterpret_cast<float*>(&vb[s]);
#pragma unroll
                    for (int e = 0; e < 4; ++e) {
                        const int gx = gx4 + e;
                        if ((unsigned)gx < (unsigned)HW) {
                            pa[e] = p1[gy * HW + gx];
                            pb[e] = p2[gy * HW + gx];
                        }
                    }
                }
            }
        }
#pragma unroll
        for (int s = 0; s < 3; ++s) {
            const int r = r0 + s * 16;
            if (r < SH) {
                float4 vs, vd;
                vs.x = va[s].x + vb[s].x; vs.y = va[s].y + vb[s].y;
                vs.z = va[s].z + vb[s].z; vs.w = va[s].w + vb[s].w;
                vd.x = va[s].x - vb[s].x; vd.y = va[s].y - vb[s].y;
                vd.z = va[s].z - vb[s].z; vd.w = va[s].w - vb[s].w;
                *reinterpret_cast<float4*>(&s_s[r * SSTR + q * 4]) = vs;
                *reinterpret_cast<float4*>(&s_d[r * SSTR + q * 4]) = vd;
            }
        }
    }
    __syncthreads();

    // ---------- Phase 2: vertical 11-tap conv of s, d, s^2, d^2 ----------
    if (tid < 296) {                 // 74 columns * 4 row-groups of 8
        const int x  = tid % 74;
        const int yb = (tid / 74) * 8;

        float aS[8], aD[8], aP[8], aQ[8];
#pragma unroll
        for (int r = 0; r < 8; ++r) { aS[r] = 0.f; aD[r] = 0.f; aP[r] = 0.f; aQ[r] = 0.f; }
#pragma unroll
        for (int jj = 0; jj < 18; ++jj) {
            const float vs  = SS(yb + jj, x);
            const float vd  = SD(yb + jj, x);
            const float vss = vs * vs;
            const float vdd = vd * vd;
#pragma unroll
            for (int r = 0; r < 8; ++r) {
                const int j = jj - r;
                if (0 <= j && j < 11) {
                    aS[r] = fmaf(GW[j], vs,  aS[r]);
                    aD[r] = fmaf(GW[j], vd,  aD[r]);
                    aP[r] = fmaf(GW[j], vss, aP[r]);
                    aQ[r] = fmaf(GW[j], vdd, aQ[r]);
                }
            }
        }
#pragma unroll
        for (int r = 0; r < 8; ++r) {
            SMID(0, yb + r, x) = aS[r];
            SMID(1, yb + r, x) = aD[r];
            SMID(2, yb + r, x) = aP[r];
            SMID(3, yb + r, x) = aQ[r];
        }
    }
    __syncthreads();

    // ---------- Phase 3: horizontal 11-tap conv + SSIM ----------
    float lsum = 0.f;
    if (tid < 256) {                  // 32 rows * 8 column-groups of 8
        const int y  = tid >> 3;
        const int xb = (tid & 7) * 8;

        float o[4][8];
#pragma unroll
        for (int q = 0; q < 4; ++q) {
            const float4* vp = reinterpret_cast<const float4*>(&SMID(q, y, xb));
            float m[20];
#pragma unroll
            for (int k = 0; k < 5; ++k) {
                const float4 v = vp[k];
                m[4 * k + 0] = v.x;
                m[4 * k + 1] = v.y;
                m[4 * k + 2] = v.z;
                m[4 * k + 3] = v.w;
            }
#pragma unroll
            for (int r = 0; r < 8; ++r) {
                float s = GW[0] * m[r];
#pragma unroll
                for (int i = 1; i < 11; ++i) s = fmaf(GW[i], m[r + i], s);
                o[q][r] = s;
            }
        }
#pragma unroll
        for (int r = 0; r < 8; ++r) {
            const float S = o[0][r], D = o[1][r], P = o[2][r], Q = o[3][r];
            const float S2 = S * S;
            const float D2 = D * D;
            const float t1 = S2 - D2;       // 4*mu1mu2
            const float t2 = S2 + D2;       // 2*(mu1^2+mu2^2)
            const float t5 = (P - Q) - t1;  // 4*sigma12
            const float t6 = (P + Q) - t2;  // 2*(sig1^2+sig2^2)
            const float num = fmaf(0.5f, t1, C1F) * fmaf(0.5f, t5, C2F);
            const float den = fmaf(0.5f, t2, C1F) * fmaf(0.5f, t6, C2F);
            lsum = fmaf(num, fast_rcp(den), lsum);
        }
    }

    // ---------- In-block reduction ----------
#pragma unroll
    for (int off = 16; off > 0; off >>= 1)
        lsum += __shfl_down_sync(0xffffffffu, lsum, off);

    __shared__ float  warp_sums[NTHREADS / 32];
    __shared__ unsigned s_last;
    const int wid  = tid >> 5;
    const int lane = tid & 31;
    if (lane == 0) warp_sums[wid] = lsum;
    __syncthreads();

    // ---------- Fence-free last-block reduction ----------
    if (tid == 0) {
        float s = 0.f;
#pragma unroll
        for (int w = 0; w < NTHREADS / 32; ++w) s += warp_sums[w];
        const int bid = (blockIdx.z * gridDim.y + blockIdx.y) * gridDim.x + blockIdx.x;
        g_part[bid] = s;
        unsigned ticket;
        asm volatile("atom.acq_rel.gpu.global.inc.u32 %0, [%1], %2;"
                     : "=r"(ticket)
                     : "l"(&g_count), "r"(NBLOCKS - 1u)
                     : "memory");
        s_last = (ticket == NBLOCKS - 1u) ? 1u : 0u;
    }
    __syncthreads();

    if (s_last) {
        double d = 0.0;
        for (int i = tid; i < (int)NBLOCKS; i += NTHREADS) d += (double)g_part[i];
#pragma unroll
        for (int off = 16; off > 0; off >>= 1)
            d += __shfl_down_sync(0xffffffffu, d, off);
        __shared__ double wsum[NTHREADS / 32];
        if (lane == 0) wsum[wid] = d;
        __syncthreads();
        if (tid == 0) {
            double t = 0.0;
#pragma unroll
            for (int w = 0; w < NTHREADS / 32; ++w) t += wsum[w];
            out[0] = (float)(t * (1.0 / NPIX));
        }
    }
}

extern "C" void kernel_launch(void* const* d_in, const int* in_sizes, int n_in,
                              void* d_out, int out_size) {
    const float* img1 = (const float*)d_in[0];
    const float* img2 = (const float*)d_in[1];
    float* out = (float*)d_out;

    const int smem_bytes = (2 * SH * SSTR + 4 * TH * SSTR) * (int)sizeof(float); // 71232
    cudaFuncSetAttribute(ssim_main_kernel,
                         cudaFuncAttributeMaxDynamicSharedMemorySize, smem_bytes);

    dim3 grid(HW / TW, HW / TH, PLANES);   // 8 x 16 x 48
    ssim_main_kernel<<<grid, NTHREADS, smem_bytes>>>(img1, img2, out);
}

// round 13
// speedup vs baseline: 1.0219x; 1.0176x over previous
#include <cuda_runtime.h>

// ---------------- problem constants ----------------
#define HW        512
#define PLANES    48          // 16 batch * 3 channels
#define NPIX      12582912.0  // 48*512*512
#define TW        64
#define TH        32
#define SW        74          // TW + 10
#define SH        42          // TH + 10
#define SSTR      76          // padded smem row stride (floats)
#define NTHREADS  320
#define NBLOCKS   6144u       // 8*16*48

#define C1F 0.0001f
#define C2F 0.0009f

// Gaussian(sigma=1.5) centered at 5.5, normalized (sum = 0.99999982).
// Tap precision is load-bearing (-3.2e-4 tap-scale error amplifies ~500x
// through the C2=9e-4 term). constexpr + literal indices -> FFMA-imm (rt=1).
__device__ constexpr float GW[11] = {
    0.00032030f, 0.00295566f, 0.01748770f, 0.06634250f, 0.16137290f,
    0.25168100f, 0.25168100f, 0.16137290f, 0.06634250f, 0.01748770f,
    0.00295566f
};

__device__ float g_part[NBLOCKS];
__device__ unsigned int g_count = 0;   // self-resetting ticket (inc wraps)

// FMA-only reciprocal: magic seed + 2 Newton steps (err ~1.4e-6, << budget).
// Avoids MUFU.RCP (rt_SMSP=8 -> chip-wide floor at 12.6M divides).
__device__ __forceinline__ float fast_rcp(float d) {
    float r = __int_as_float(0x7EF311C3 - __float_as_int(d));
#pragma unroll
    for (int it = 0; it < 2; ++it) {
        float t = fmaf(-d, r, 1.0f);
        r = fmaf(r, t, r);
    }
    return r;
}

// SSIM via sum/difference transform (4 convolutions):
//   s=a+b, d=a-b;  S=conv(s), D=conv(d), P=conv(s^2), Q=conv(d^2)
//   4*mu1mu2 = S^2-D^2;  2*(mu1^2+mu2^2) = S^2+D^2
//   4*sigma12 = (P-Q)-(S^2-D^2);  2*(sig1^2+sig2^2) = (P+Q)-(S^2+D^2)

#define SS(r, c)      s_s[(r) * SSTR + (c)]
#define SD(r, c)      s_d[(r) * SSTR + (c)]
#define SMID(q, r, c) s_mid[((q) * TH + (r)) * SSTR + (c)]

// R10 body verbatim; only the occupancy bound changed (2 -> 3).
// 3 blocks/SM: smem 3*64,448=193KB < 228KB carveout; regs 56 <= 68 cap.
// R7 reinterpreted: occupancy DID help there but was cancelled by +9%
// instructions; this applies the occupancy gain with zero instruction change.
__global__ void __launch_bounds__(NTHREADS, 3)
ssim_main_kernel(const float* __restrict__ img1, const float* __restrict__ img2,
                 float* __restrict__ out) {
    extern __shared__ float smem[];
    float* s_s   = smem;                         // SH * SSTR  (a+b)
    float* s_d   = smem + SH * SSTR;             // SH * SSTR  (a-b)
    float* s_mid = smem + 2 * SH * SSTR;         // 4 * TH * SSTR

    const int tid   = threadIdx.x;
    const int plane = blockIdx.z;
    const int x0    = blockIdx.x * TW;
    const int y0    = blockIdx.y * TH;

    const float* __restrict__ p1 = img1 + (size_t)plane * HW * HW;
    const float* __restrict__ p2 = img2 + (size_t)plane * HW * HW;

    // ---------- Phase 1: load halo, store (a+b, a-b) ----------
#pragma unroll
    for (int ii = 0; ii < (SH * SW + NTHREADS - 1) / NTHREADS; ++ii) {
        const int i = tid + ii * NTHREADS;
        if (i < SH * SW) {
            const int r  = i / SW;
            const int c  = i - r * SW;
            const int gy = y0 - 5 + r;
            const int gx = x0 - 5 + c;
            float a = 0.f, b = 0.f;
            if ((unsigned)gy < (unsigned)HW && (unsigned)gx < (unsigned)HW) {
                const int gi = gy * HW + gx;
                a = p1[gi];
                b = p2[gi];
            }
            SS(r, c) = a + b;
            SD(r, c) = a - b;
        }
    }
    __syncthreads();

    // ---------- Phase 2: vertical 11-tap conv of s, d, s^2, d^2 ----------
    if (tid < 296) {                 // 74 columns * 4 row-groups of 8
        const int x  = tid % 74;
        const int yb = (tid / 74) * 8;

        float aS[8], aD[8], aP[8], aQ[8];
#pragma unroll
        for (int r = 0; r < 8; ++r) { aS[r] = 0.f; aD[r] = 0.f; aP[r] = 0.f; aQ[r] = 0.f; }
#pragma unroll
        for (int jj = 0; jj < 18; ++jj) {
            const float vs  = SS(yb + jj, x);
            const float vd  = SD(yb + jj, x);
            const float vss = vs * vs;
            const float vdd = vd * vd;
#pragma unroll
            for (int r = 0; r < 8; ++r) {
                const int j = jj - r;
                if (0 <= j && j < 11) {
                    aS[r] = fmaf(GW[j], vs,  aS[r]);
                    aD[r] = fmaf(GW[j], vd,  aD[r]);
                    aP[r] = fmaf(GW[j], vss, aP[r]);
                    aQ[r] = fmaf(GW[j], vdd, aQ[r]);
                }
            }
        }
#pragma unroll
        for (int r = 0; r < 8; ++r) {
            SMID(0, yb + r, x) = aS[r];
            SMID(1, yb + r, x) = aD[r];
            SMID(2, yb + r, x) = aP[r];
            SMID(3, yb + r, x) = aQ[r];
        }
    }
    __syncthreads();

    // ---------- Phase 3: horizontal 11-tap conv + SSIM ----------
    float lsum = 0.f;
    if (tid < 256) {                  // 32 rows * 8 column-groups of 8
        const int y  = tid >> 3;
        const int xb = (tid & 7) * 8;

        float o[4][8];
#pragma unroll
        for (int q = 0; q < 4; ++q) {
            const float4* vp = reinterpret_cast<const float4*>(&SMID(q, y, xb));
            float m[20];
#pragma unroll
            for (int k = 0; k < 5; ++k) {
                const float4 v = vp[k];
                m[4 * k + 0] = v.x;
                m[4 * k + 1] = v.y;
                m[4 * k + 2] = v.z;
                m[4 * k + 3] = v.w;
            }
#pragma unroll
            for (int r = 0; r < 8; ++r) {
                float s = GW[0] * m[r];
#pragma unroll
                for (int i = 1; i < 11; ++i) s = fmaf(GW[i], m[r + i], s);
                o[q][r] = s;
            }
        }
#pragma unroll
        for (int r = 0; r < 8; ++r) {
            const float S = o[0][r], D = o[1][r], P = o[2][r], Q = o[3][r];
            const float S2 = S * S;
            const float D2 = D * D;
            const float t1 = S2 - D2;       // 4*mu1mu2
            const float t2 = S2 + D2;       // 2*(mu1^2+mu2^2)
            const float t5 = (P - Q) - t1;  // 4*sigma12
            const float t6 = (P + Q) - t2;  // 2*(sig1^2+sig2^2)
            const float num = fmaf(0.5f, t1, C1F) * fmaf(0.5f, t5, C2F);
            const float den = fmaf(0.5f, t2, C1F) * fmaf(0.5f, t6, C2F);
            lsum = fmaf(num, fast_rcp(den), lsum);
        }
    }

    // ---------- In-block reduction ----------
#pragma unroll
    for (int off = 16; off > 0; off >>= 1)
        lsum += __shfl_down_sync(0xffffffffu, lsum, off);

    __shared__ float  warp_sums[NTHREADS / 32];
    __shared__ unsigned s_last;
    const int wid  = tid >> 5;
    const int lane = tid & 31;
    if (lane == 0) warp_sums[wid] = lsum;
    __syncthreads();

    // ---------- Fence-free last-block reduction ----------
    if (tid == 0) {
        float s = 0.f;
#pragma unroll
        for (int w = 0; w < NTHREADS / 32; ++w) s += warp_sums[w];
        const int bid = (blockIdx.z * gridDim.y + blockIdx.y) * gridDim.x + blockIdx.x;
        g_part[bid] = s;
        unsigned ticket;
        asm volatile("atom.acq_rel.gpu.global.inc.u32 %0, [%1], %2;"
                     : "=r"(ticket)
                     : "l"(&g_count), "r"(NBLOCKS - 1u)
                     : "memory");
        s_last = (ticket == NBLOCKS - 1u) ? 1u : 0u;
    }
    __syncthreads();

    if (s_last) {
        double d = 0.0;
        for (int i = tid; i < (int)NBLOCKS; i += NTHREADS) d += (double)g_part[i];
#pragma unroll
        for (int off = 16; off > 0; off >>= 1)
            d += __shfl_down_sync(0xffffffffu, d, off);
        __shared__ double wsum[NTHREADS / 32];
        if (lane == 0) wsum[wid] = d;
        __syncthreads();
        if (tid == 0) {
            double t = 0.0;
#pragma unroll
            for (int w = 0; w < NTHREADS / 32; ++w) t += wsum[w];
            out[0] = (float)(t * (1.0 / NPIX));
        }
    }
}

extern "C" void kernel_launch(void* const* d_in, const int* in_sizes, int n_in,
                              void* d_out, int out_size) {
    const float* img1 = (const float*)d_in[0];
    const float* img2 = (const float*)d_in[1];
    float* out = (float*)d_out;

    const int smem_bytes = (2 * SH * SSTR + 4 * TH * SSTR) * (int)sizeof(float); // 64448
    cudaFuncSetAttribute(ssim_main_kernel,
                         cudaFuncAttributeMaxDynamicSharedMemorySize, smem_bytes);

    dim3 grid(HW / TW, HW / TH, PLANES);   // 8 x 16 x 48
    ssim_main_kernel<<<grid, NTHREADS, smem_bytes>>>(img1, img2, out);
}

// round 16
// speedup vs baseline: 1.0395x; 1.0172x over previous
#include <cuda_runtime.h>

// ---------------- problem constants ----------------
#define HW        512
#define PLANES    48          // 16 batch * 3 channels
#define NPIX      12582912.0  // 48*512*512
#define TW        64
#define TH        32
#define SW        74          // TW + 10
#define SH        42          // TH + 10
#define SSTR      76          // row stride: float2 units for s_sd, floats for mid
#define NTHREADS  320
#define NBLOCKS   6144u       // 8*16*48

#define C1F 0.0001f
#define C2F 0.0009f

typedef unsigned long long u64;

// Gaussian(sigma=1.5) centered at 5.5, normalized (sum = 0.99999982).
// Tap precision is load-bearing (-3.2e-4 tap-scale error amplifies ~500x
// through the C2=9e-4 term).
// SYMMETRY (R15 post-mortem): center is 5.5 -> GW[j] == GW[11-j] for j=1..10;
// GW[0] is unpaired. The R14/R15 failures (identical rel_err 31.6 across two
// pack2 implementations) were the wi map using 10-j, shifting every upper-half
// tap by one. pack2 was innocent.
__device__ constexpr float GW[11] = {
    0.00032030f, 0.00295566f, 0.01748770f, 0.06634250f, 0.16137290f,
    0.25168100f, 0.25168100f, 0.16137290f, 0.06634250f, 0.01748770f,
    0.00295566f
};

__device__ float g_part[NBLOCKS];
__device__ unsigned int g_count = 0;   // self-resetting ticket (inc wraps)

// ---- packed f32x2 (Blackwell FFMA2/FMUL2; PTX-only). One issue slot, two
// fp32 lanes; per-lane fma-pipe cost equals FFMA-imm (R8 measurement). ----
#define FMA_F32X2(d, a, b, c) \
    asm("fma.rn.f32x2 %0, %1, %2, %3;" : "=l"(d) : "l"(a), "l"(b), "l"(c))
#define MUL_F32X2(d, a, b) \
    asm("mul.rn.f32x2 %0, %1, %2;" : "=l"(d) : "l"(a), "l"(b))

__device__ __forceinline__ u64 pack2(float lo, float hi) {
    return ((u64)__float_as_uint(hi) << 32) | (u64)__float_as_uint(lo);
}
__device__ __forceinline__ float lo2(u64 v) { return __uint_as_float((unsigned)v); }
__device__ __forceinline__ float hi2(u64 v) { return __uint_as_float((unsigned)(v >> 32)); }

// FMA-only reciprocal: magic seed + 2 Newton steps (err ~1.4e-6, << budget).
// Avoids MUFU.RCP (rt_SMSP=8 -> chip-wide floor at 12.6M divides).
__device__ __forceinline__ float fast_rcp(float d) {
    float r = __int_as_float(0x7EF311C3 - __float_as_int(d));
#pragma unroll
    for (int it = 0; it < 2; ++it) {
        float t = fmaf(-d, r, 1.0f);
        r = fmaf(r, t, r);
    }
    return r;
}

// SSIM via sum/difference transform (4 convolutions = exactly 2 FFMA2 pairs):
//   s=a+b, d=a-b;  S=conv(s), D=conv(d), P=conv(s^2), Q=conv(d^2)
//   4*mu1mu2 = S^2-D^2;  2*(mu1^2+mu2^2) = S^2+D^2
//   4*sigma12 = (P-Q)-(S^2-D^2);  2*(sig1^2+sig2^2) = (P+Q)-(S^2+D^2)

#define SMID(q, r, c) s_mid[((q) * TH + (r)) * SSTR + (c)]

__global__ void __launch_bounds__(NTHREADS, 3)
ssim_main_kernel(const float* __restrict__ img1, const float* __restrict__ img2,
                 float* __restrict__ out) {
    extern __shared__ u64 smem8[];
    u64*   s_sd  = smem8;                        // SH*SSTR u64: (s,d) interleaved
    float* s_mid = (float*)(smem8 + SH * SSTR);  // 4 scalar planes TH*SSTR

    const int tid   = threadIdx.x;
    const int plane = blockIdx.z;
    const int x0    = blockIdx.x * TW;
    const int y0    = blockIdx.y * TH;

    const float* __restrict__ p1 = img1 + (size_t)plane * HW * HW;
    const float* __restrict__ p2 = img2 + (size_t)plane * HW * HW;

    // 6 packed weights: W2[i] covers GW[i] for i=0..5; taps j>=6 alias via 11-j
    u64 W2[6];
#pragma unroll
    for (int i = 0; i < 6; ++i) W2[i] = pack2(GW[i], GW[i]);

    // ---------- Phase 1: load halo, store packed (a+b, a-b) via STS.64 ----
    if (tid < 296) {
        const int x  = tid % 74;
        const int r0 = tid / 74;
        const int gx = x0 - 5 + x;
        const bool xin = (unsigned)gx < (unsigned)HW;
#pragma unroll
        for (int rr = 0; rr < 11; ++rr) {
            const int r = r0 + rr * 4;
            if (r < SH) {
                const int gy = y0 - 5 + r;
                float a = 0.f, b = 0.f;
                if (xin && (unsigned)gy < (unsigned)HW) {
                    const int gi = gy * HW + gx;
                    a = p1[gi];
                    b = p2[gi];
                }
                s_sd[r * SSTR + x] = pack2(a + b, a - b);
            }
        }
    }
    __syncthreads();

    // ---------- Phase 2: vertical 11-tap conv via FFMA2 ----------
    // per tap-row: 2 FFMA2 instead of 4 FFMA (issue slots halved; fma-pipe
    // cycles identical). Loads: 1 LDS.64 per tap (was 2 LDS.32).
    if (tid < 296) {                 // 74 columns * 4 row-groups of 8
        const int x  = tid % 74;
        const int yb = (tid / 74) * 8;

        u64 aSD[8], aPQ[8];
#pragma unroll
        for (int r = 0; r < 8; ++r) { aSD[r] = 0ull; aPQ[r] = 0ull; }
#pragma unroll
        for (int jj = 0; jj < 18; ++jj) {
            const u64 p01 = s_sd[(yb + jj) * SSTR + x];   // (s, d)
            u64 p23;
            MUL_F32X2(p23, p01, p01);                     // (s^2, d^2)
#pragma unroll
            for (int r = 0; r < 8; ++r) {
                const int j = jj - r;
                if (0 <= j && j < 11) {
                    const int wi = (j < 6) ? j : 11 - j;  // FIXED: GW[j]==GW[11-j]
                    FMA_F32X2(aSD[r], p01, W2[wi], aSD[r]);
                    FMA_F32X2(aPQ[r], p23, W2[wi], aPQ[r]);
                }
            }
        }
        // unpack -> scalar mid planes, phase 3 stays the proven float4 form
#pragma unroll
        for (int r = 0; r < 8; ++r) {
            SMID(0, yb + r, x) = lo2(aSD[r]);
            SMID(1, yb + r, x) = hi2(aSD[r]);
            SMID(2, yb + r, x) = lo2(aPQ[r]);
            SMID(3, yb + r, x) = hi2(aPQ[r]);
        }
    }
    __syncthreads();

    // ---------- Phase 3: horizontal 11-tap conv + SSIM (R10/R13 winner form) ----
    float lsum = 0.f;
    if (tid < 256) {                  // 32 rows * 8 column-groups of 8
        const int y  = tid >> 3;
        const int xb = (tid & 7) * 8;

        float o[4][8];
#pragma unroll
        for (int q = 0; q < 4; ++q) {
            const float4* vp = reinterpret_cast<const float4*>(&SMID(q, y, xb));
            float m[20];
#pragma unroll
            for (int k = 0; k < 5; ++k) {
                const float4 v = vp[k];
                m[4 * k + 0] = v.x;
                m[4 * k + 1] = v.y;
                m[4 * k + 2] = v.z;
                m[4 * k + 3] = v.w;
            }
#pragma unroll
            for (int r = 0; r < 8; ++r) {
                float s = GW[0] * m[r];
#pragma unroll
                for (int i = 1; i < 11; ++i) s = fmaf(GW[i], m[r + i], s);
                o[q][r] = s;
            }
        }
#pragma unroll
        for (int r = 0; r < 8; ++r) {
            const float S = o[0][r], D = o[1][r], P = o[2][r], Q = o[3][r];
            const float S2 = S * S;
            const float D2 = D * D;
            const float t1 = S2 - D2;       // 4*mu1mu2
            const float t2 = S2 + D2;       // 2*(mu1^2+mu2^2)
            const float t5 = (P - Q) - t1;  // 4*sigma12
            const float t6 = (P + Q) - t2;  // 2*(sig1^2+sig2^2)
            const float num = fmaf(0.5f, t1, C1F) * fmaf(0.5f, t5, C2F);
            const float den = fmaf(0.5f, t2, C1F) * fmaf(0.5f, t6, C2F);
            lsum = fmaf(num, fast_rcp(den), lsum);
        }
    }

    // ---------- In-block reduction ----------
#pragma unroll
    for (int off = 16; off > 0; off >>= 1)
        lsum += __shfl_down_sync(0xffffffffu, lsum, off);

    __shared__ float  warp_sums[NTHREADS / 32];
    __shared__ unsigned s_last;
    const int wid  = tid >> 5;
    const int lane = tid & 31;
    if (lane == 0) warp_sums[wid] = lsum;
    __syncthreads();

    // ---------- Fence-free last-block reduction ----------
    if (tid == 0) {
        float s = 0.f;
#pragma unroll
        for (int w = 0; w < NTHREADS / 32; ++w) s += warp_sums[w];
        const int bid = (blockIdx.z * gridDim.y + blockIdx.y) * gridDim.x + blockIdx.x;
        g_part[bid] = s;
        unsigned ticket;
        asm volatile("atom.acq_rel.gpu.global.inc.u32 %0, [%1], %2;"
                     : "=r"(ticket)
                     : "l"(&g_count), "r"(NBLOCKS - 1u)
                     : "memory");
        s_last = (ticket == NBLOCKS - 1u) ? 1u : 0u;
    }
    __syncthreads();

    if (s_last) {
        double d = 0.0;
        for (int i = tid; i < (int)NBLOCKS; i += NTHREADS) d += (double)g_part[i];
#pragma unroll
        for (int off = 16; off > 0; off >>= 1)
            d += __shfl_down_sync(0xffffffffu, d, off);
        __shared__ double wsum[NTHREADS / 32];
        if (lane == 0) wsum[wid] = d;
        __syncthreads();
        if (tid == 0) {
            double t = 0.0;
#pragma unroll
            for (int w = 0; w < NTHREADS / 32; ++w) t += wsum[w];
            out[0] = (float)(t * (1.0 / NPIX));
        }
    }
}

extern "C" void kernel_launch(void* const* d_in, const int* in_sizes, int n_in,
                              void* d_out, int out_size) {
    const float* img1 = (const float*)d_in[0];
    const float* img2 = (const float*)d_in[1];
    float* out = (float*)d_out;

    // s_sd 42*76*8 = 25,536 B + mid 4*32*76*4 = 38,912 B -> 64,448 B (3 blocks/SM)
    const int smem_bytes = SH * SSTR * 8 + 4 * TH * SSTR * 4;
    cudaFuncSetAttribute(ssim_main_kernel,
                         cudaFuncAttributeMaxDynamicSharedMemorySize, smem_bytes);

    dim3 grid(HW / TW, HW / TH, PLANES);   // 8 x 16 x 48
    ssim_main_kernel<<<grid, NTHREADS, smem_bytes>>>(img1, img2, out);
}

// round 17
// speedup vs baseline: 1.1529x; 1.1091x over previous
#include <cuda_runtime.h>

// ---------------- problem constants ----------------
#define HW        512
#define PLANES    48          // 16 batch * 3 channels
#define NPIX      12582912.0  // 48*512*512
#define TW        64
#define TH        32
#define SW        74          // TW + 10
#define SH        42          // TH + 10
#define SSTR      76          // s_sd row stride (u64 units)
#define MSTR      77          // mid-plane row stride (u64 units): lane*154 mod 32
                              // spans all banks -> conflict-free LDS.64 in phase 3
#define NTHREADS  320
#define NBLOCKS   6144u       // 8*16*48

#define C1F 0.0001f
#define C2F 0.0009f

typedef unsigned long long u64;

// Gaussian(sigma=1.5) centered at 5.5, normalized (sum = 0.99999982).
// Tap precision is load-bearing. SYMMETRY: GW[j]==GW[11-j] for j=1..10 (R16-
// validated wi map: j<6 ? j : 11-j).
__device__ constexpr float GW[11] = {
    0.00032030f, 0.00295566f, 0.01748770f, 0.06634250f, 0.16137290f,
    0.25168100f, 0.25168100f, 0.16137290f, 0.06634250f, 0.01748770f,
    0.00295566f
};

__device__ float g_part[NBLOCKS];
__device__ unsigned int g_count = 0;   // self-resetting ticket (inc wraps)

// ---- packed f32x2 (Blackwell FFMA2/FMUL2; PTX-only) ----
#define FMA_F32X2(d, a, b, c) \
    asm("fma.rn.f32x2 %0, %1, %2, %3;" : "=l"(d) : "l"(a), "l"(b), "l"(c))
#define MUL_F32X2(d, a, b) \
    asm("mul.rn.f32x2 %0, %1, %2;" : "=l"(d) : "l"(a), "l"(b))

// R8/R16-validated pack: lo in low 32 bits.
__device__ __forceinline__ u64 pack2(float lo, float hi) {
    return ((u64)__float_as_uint(hi) << 32) | (u64)__float_as_uint(lo);
}
__device__ __forceinline__ float lo2(u64 v) { return __uint_as_float((unsigned)v); }
__device__ __forceinline__ float hi2(u64 v) { return __uint_as_float((unsigned)(v >> 32)); }

// FMA-only reciprocal: magic seed + 2 Newton steps (err ~1.4e-6, << budget).
__device__ __forceinline__ float fast_rcp(float d) {
    float r = __int_as_float(0x7EF311C3 - __float_as_int(d));
#pragma unroll
    for (int it = 0; it < 2; ++it) {
        float t = fmaf(-d, r, 1.0f);
        r = fmaf(r, t, r);
    }
    return r;
}

// SSIM via sum/difference transform (4 convolutions = 2 FFMA2 pairs):
//   s=a+b, d=a-b;  S=conv(s), D=conv(d), P=conv(s^2), Q=conv(d^2)
//   4*mu1mu2 = S^2-D^2;  2*(mu1^2+mu2^2) = S^2+D^2
//   4*sigma12 = (P-Q)-(S^2-D^2);  2*(sig1^2+sig2^2) = (P+Q)-(S^2+D^2)

__global__ void __launch_bounds__(NTHREADS, 3)
ssim_main_kernel(const float* __restrict__ img1, const float* __restrict__ img2,
                 float* __restrict__ out) {
    extern __shared__ u64 smem8[];
    u64* s_sd    = smem8;                      // SH*SSTR u64: (s,d) input halo
    u64* s_midSD = s_sd + SH * SSTR;           // TH*MSTR u64: (S,D) after vconv
    u64* s_midPQ = s_midSD + TH * MSTR;        // TH*MSTR u64: (P,Q) after vconv

    const int tid   = threadIdx.x;
    const int plane = blockIdx.z;
    const int x0    = blockIdx.x * TW;
    const int y0    = blockIdx.y * TH;

    const float* __restrict__ p1 = img1 + (size_t)plane * HW * HW;
    const float* __restrict__ p2 = img2 + (size_t)plane * HW * HW;

    // 6 packed weights: W2[i]=GW[i] for i=0..5; taps j>=6 alias via 11-j
    u64 W2[6];
#pragma unroll
    for (int i = 0; i < 6; ++i) W2[i] = pack2(GW[i], GW[i]);

    // ---------- Phase 1: load halo, store packed (a+b, a-b) via STS.64 ----
    if (tid < 296) {
        const int x  = tid % 74;
        const int r0 = tid / 74;
        const int gx = x0 - 5 + x;
        const bool xin = (unsigned)gx < (unsigned)HW;
#pragma unroll
        for (int rr = 0; rr < 11; ++rr) {
            const int r = r0 + rr * 4;
            if (r < SH) {
                const int gy = y0 - 5 + r;
                float a = 0.f, b = 0.f;
                if (xin && (unsigned)gy < (unsigned)HW) {
                    const int gi = gy * HW + gx;
                    a = p1[gi];
                    b = p2[gi];
                }
                s_sd[r * SSTR + x] = pack2(a + b, a - b);
            }
        }
    }
    __syncthreads();

    // ---------- Phase 2: vertical 11-tap conv via FFMA2, packed stores ----
    if (tid < 296) {                 // 74 columns * 4 row-groups of 8
        const int x  = tid % 74;
        const int yb = (tid / 74) * 8;

        u64 aSD[8], aPQ[8];
#pragma unroll
        for (int r = 0; r < 8; ++r) { aSD[r] = 0ull; aPQ[r] = 0ull; }
#pragma unroll
        for (int jj = 0; jj < 18; ++jj) {
            const u64 p01 = s_sd[(yb + jj) * SSTR + x];   // (s, d)
            u64 p23;
            MUL_F32X2(p23, p01, p01);                     // (s^2, d^2)
#pragma unroll
            for (int r = 0; r < 8; ++r) {
                const int j = jj - r;
                if (0 <= j && j < 11) {
                    const int wi = (j < 6) ? j : 11 - j;  // GW[j]==GW[11-j]
                    FMA_F32X2(aSD[r], p01, W2[wi], aSD[r]);
                    FMA_F32X2(aPQ[r], p23, W2[wi], aPQ[r]);
                }
            }
        }
#pragma unroll
        for (int r = 0; r < 8; ++r) {
            s_midSD[(yb + r) * MSTR + x] = aSD[r];
            s_midPQ[(yb + r) * MSTR + x] = aPQ[r];
        }
    }
    __syncthreads();

    // ---------- Phase 3: horizontal 11-tap conv (FFMA2) + SSIM ----------
    // Remap: lane = row (y), warp = 8-px col-group. With MSTR=77 the 32 lanes'
    // row bases hit 32 distinct banks -> LDS.64 stream is conflict-free.
    float lsum = 0.f;
    if (tid < 256) {
        const int y  = tid & 31;          // lane = row
        const int w  = tid >> 5;          // warp = col-group 0..7
        const int base = y * MSTR + w * 8;

        u64 oSD[8], oPQ[8];
#pragma unroll
        for (int r = 0; r < 8; ++r) { oSD[r] = 0ull; oPQ[r] = 0ull; }

#pragma unroll
        for (int i = 0; i < 18; ++i) {
            const u64 m = s_midSD[base + i];
#pragma unroll
            for (int r = 0; r < 8; ++r) {
                const int j = i - r;
                if (0 <= j && j < 11) {
                    const int wi = (j < 6) ? j : 11 - j;
                    FMA_F32X2(oSD[r], m, W2[wi], oSD[r]);
                }
            }
        }
#pragma unroll
        for (int i = 0; i < 18; ++i) {
            const u64 m = s_midPQ[base + i];
#pragma unroll
            for (int r = 0; r < 8; ++r) {
                const int j = i - r;
                if (0 <= j && j < 11) {
                    const int wi = (j < 6) ? j : 11 - j;
                    FMA_F32X2(oPQ[r], m, W2[wi], oPQ[r]);
                }
            }
        }

#pragma unroll
        for (int r = 0; r < 8; ++r) {
            u64 sq;
            MUL_F32X2(sq, oSD[r], oSD[r]);       // (S^2, D^2)
            const float S2 = lo2(sq), D2 = hi2(sq);
            const float P  = lo2(oPQ[r]), Q = hi2(oPQ[r]);
            const float t1 = S2 - D2;            // 4*mu1mu2
            const float t2 = S2 + D2;            // 2*(mu1^2+mu2^2)
            const float t5 = (P - Q) - t1;       // 4*sigma12
            const float t6 = (P + Q) - t2;       // 2*(sig1^2+sig2^2)
            const float num = fmaf(0.5f, t1, C1F) * fmaf(0.5f, t5, C2F);
            const float den = fmaf(0.5f, t2, C1F) * fmaf(0.5f, t6, C2F);
            lsum = fmaf(num, fast_rcp(den), lsum);
        }
    }

    // ---------- In-block reduction ----------
#pragma unroll
    for (int off = 16; off > 0; off >>= 1)
        lsum += __shfl_down_sync(0xffffffffu, lsum, off);

    __shared__ float  warp_sums[NTHREADS / 32];
    __shared__ unsigned s_last;
    const int wid  = tid >> 5;
    const int lane = tid & 31;
    if (lane == 0) warp_sums[wid] = lsum;
    __syncthreads();

    // ---------- Fence-free last-block reduction ----------
    if (tid == 0) {
        float s = 0.f;
#pragma unroll
        for (int w = 0; w < NTHREADS / 32; ++w) s += warp_sums[w];
        const int bid = (blockIdx.z * gridDim.y + blockIdx.y) * gridDim.x + blockIdx.x;
        g_part[bid] = s;
        unsigned ticket;
        asm volatile("atom.acq_rel.gpu.global.inc.u32 %0, [%1], %2;"
                     : "=r"(ticket)
                     : "l"(&g_count), "r"(NBLOCKS - 1u)
                     : "memory");
        s_last = (ticket == NBLOCKS - 1u) ? 1u : 0u;
    }
    __syncthreads();

    if (s_last) {
        double d = 0.0;
        for (int i = tid; i < (int)NBLOCKS; i += NTHREADS) d += (double)g_part[i];
#pragma unroll
        for (int off = 16; off > 0; off >>= 1)
            d += __shfl_down_sync(0xffffffffu, d, off);
        __shared__ double wsum[NTHREADS / 32];
        if (lane == 0) wsum[wid] = d;
        __syncthreads();
        if (tid == 0) {
            double t = 0.0;
#pragma unroll
            for (int w = 0; w < NTHREADS / 32; ++w) t += wsum[w];
            out[0] = (float)(t * (1.0 / NPIX));
        }
    }
}

extern "C" void kernel_launch(void* const* d_in, const int* in_sizes, int n_in,
                              void* d_out, int out_size) {
    const float* img1 = (const float*)d_in[0];
    const float* img2 = (const float*)d_in[1];
    float* out = (float*)d_out;

    // s_sd 42*76*8 = 25,536 B + 2 packed mids 32*77*8*2 = 39,424 B -> 64,960 B
    // (3 blocks/SM: 194,880 B < 227 KB carveout)
    const int smem_bytes = (SH * SSTR + 2 * TH * MSTR) * 8;
    cudaFuncSetAttribute(ssim_main_kernel,
                         cudaFuncAttributeMaxDynamicSharedMemorySize, smem_bytes);

    dim3 grid(HW / TW, HW / TH, PLANES);   // 8 x 16 x 48
    ssim_main_kernel<<<grid, NTHREADS, smem_bytes>>>(img1, img2, out);
}